// round 5
// baseline (speedup 1.0000x reference)
#include <cuda_runtime.h>
#include <cuda_bf16.h>

// Problem constants (fixed by the reference)
#define BATCH 4
#define NCH 3
#define NCLS 20
#define HH 512
#define WW 512
#define MAXB 50
#define NSLICE 16
#define ROWG 8                         // row-groups per block
#define LANES 32                       // lanes per row-group (x, each handles float4)
#define ROWSTRIDE (NSLICE * ROWG)      // 128-way row interleave per box
#define NPARTS (BATCH * MAXB * NSLICE)
#define TOTAL_BLOCKS (BATCH * MAXB * NSLICE)

// Scratch for deterministic two-stage reduction (no atomics on floats, no allocation)
__device__ float g_partials[NPARTS];
__device__ int   g_counter = 0;        // last-block-done counter; reset by last block

// One block = one (batch, box, row-slice). 256 threads = 8 row-groups x 32 lanes.
// Each lane processes a float4 -> 128 columns per vector step.
// The last block to finish performs the final deterministic reduction in-kernel.
__global__ void __launch_bounds__(256) box_sum_kernel(
    const float* __restrict__ y_fcn,    // [B, NCLS*NCH, H, W]
    const float* __restrict__ im_data,  // [B, NCH, H, W]
    const int*   __restrict__ gt_boxes, // [B, MAXB, 5] (x1,y1,x2,y2,cls)
    const int*   __restrict__ num_boxes,// [B]
    float*       __restrict__ out
) {
    const int bb    = blockIdx.x;           // 0 .. B*MAXB-1
    const int slice = blockIdx.y;           // 0 .. NSLICE-1
    const int b     = bb / MAXB;
    const int box   = bb % MAXB;
    const int tid   = threadIdx.x;

    float acc = 0.0f;

    if (box < __ldg(&num_boxes[b])) {
        const int* g = gt_boxes + bb * 5;
        const int x1  = __ldg(&g[0]);
        const int y1  = __ldg(&g[1]);
        const int x2  = __ldg(&g[2]);
        const int y2  = __ldg(&g[3]);
        const int cls = __ldg(&g[4]);

        const int tx = tid & (LANES - 1);      // 0..31
        const int ty = tid / LANES;            // 0..7
        const int rowWorker = slice * ROWG + ty;   // 0..127

        const size_t plane = (size_t)HH * WW;
        // class cls occupies channels [cls*NCH, (cls+1)*NCH) of y_fcn
        const float* yb = y_fcn   + ((size_t)b * (NCLS * NCH) + (size_t)cls * NCH) * plane;
        const float* ib = im_data + (size_t)b * NCH * plane;

        // Aligned interior for float4 path
        const int vx1 = (x1 + 3) & ~3;
        const int vx2 = x2 & ~3;

        for (int r = y1 + rowWorker; r < y2; r += ROWSTRIDE) {
            const float* yr0 = yb + (size_t)r * WW;
            const float* yr1 = yr0 + plane;
            const float* yr2 = yr1 + plane;
            const float* ir0 = ib + (size_t)r * WW;
            const float* ir1 = ir0 + plane;
            const float* ir2 = ir1 + plane;

            if (vx1 < vx2) {
                // scalar head: [x1, vx1), width 0..3
                for (int x = x1 + tx; x < vx1; x += LANES) {
                    float d0 = ir0[x] - yr0[x];
                    float d1 = ir1[x] - yr1[x];
                    float d2 = ir2[x] - yr2[x];
                    acc = fmaf(d0, d0, acc);
                    acc = fmaf(d1, d1, acc);
                    acc = fmaf(d2, d2, acc);
                }
                // vector body: [vx1, vx2), 32 lanes x float4 = 128 cols per step
                for (int x = vx1 + tx * 4; x < vx2; x += LANES * 4) {
                    float4 a0 = *(const float4*)(ir0 + x);
                    float4 c0 = *(const float4*)(yr0 + x);
                    float4 a1 = *(const float4*)(ir1 + x);
                    float4 c1 = *(const float4*)(yr1 + x);
                    float4 a2 = *(const float4*)(ir2 + x);
                    float4 c2 = *(const float4*)(yr2 + x);
                    float d;
                    d = a0.x - c0.x; acc = fmaf(d, d, acc);
                    d = a0.y - c0.y; acc = fmaf(d, d, acc);
                    d = a0.z - c0.z; acc = fmaf(d, d, acc);
                    d = a0.w - c0.w; acc = fmaf(d, d, acc);
                    d = a1.x - c1.x; acc = fmaf(d, d, acc);
                    d = a1.y - c1.y; acc = fmaf(d, d, acc);
                    d = a1.z - c1.z; acc = fmaf(d, d, acc);
                    d = a1.w - c1.w; acc = fmaf(d, d, acc);
                    d = a2.x - c2.x; acc = fmaf(d, d, acc);
                    d = a2.y - c2.y; acc = fmaf(d, d, acc);
                    d = a2.z - c2.z; acc = fmaf(d, d, acc);
                    d = a2.w - c2.w; acc = fmaf(d, d, acc);
                }
                // scalar tail: [vx2, x2), width 0..3
                for (int x = vx2 + tx; x < x2; x += LANES) {
                    float d0 = ir0[x] - yr0[x];
                    float d1 = ir1[x] - yr1[x];
                    float d2 = ir2[x] - yr2[x];
                    acc = fmaf(d0, d0, acc);
                    acc = fmaf(d1, d1, acc);
                    acc = fmaf(d2, d2, acc);
                }
            } else {
                // narrow box (< 4 aligned cols): all scalar
                for (int x = x1 + tx; x < x2; x += LANES) {
                    float d0 = ir0[x] - yr0[x];
                    float d1 = ir1[x] - yr1[x];
                    float d2 = ir2[x] - yr2[x];
                    acc = fmaf(d0, d0, acc);
                    acc = fmaf(d1, d1, acc);
                    acc = fmaf(d2, d2, acc);
                }
            }
        }

        const int area = (y2 - y1) * (x2 - x1);
        const float inv_denom = 1.0f / (float)(NCH * (area > 1 ? area : 1));
        acc *= inv_denom;   // linear in acc -> identical to scaling the block sum
    }

    // Deterministic block reduction: warp shuffles + shared across 8 warps
    #pragma unroll
    for (int off = 16; off > 0; off >>= 1)
        acc += __shfl_down_sync(0xFFFFFFFFu, acc, off);

    __shared__ float warp_sums[8];
    const int lane = tid & 31;
    const int wid  = tid >> 5;
    if (lane == 0) warp_sums[wid] = acc;
    __syncthreads();

    if (wid == 0) {
        float s = (lane < 8) ? warp_sums[lane] : 0.0f;
        #pragma unroll
        for (int off = 4; off > 0; off >>= 1)
            s += __shfl_down_sync(0xFFFFFFFFu, s, off);
        if (lane == 0)
            g_partials[bb * NSLICE + slice] = s;
    }

    // ---- last-block-done fused finalize ----
    __shared__ bool is_last;
    if (tid == 0) {
        __threadfence();                       // publish our partial
        int prev = atomicAdd(&g_counter, 1);
        is_last = (prev == TOTAL_BLOCKS - 1);
    }
    __syncthreads();

    if (is_last) {
        __threadfence();                       // see everyone's partials

        float s = 0.0f;
        #pragma unroll 4
        for (int i = tid; i < NPARTS; i += 256)
            s += g_partials[i];                // fixed order -> deterministic

        #pragma unroll
        for (int off = 16; off > 0; off >>= 1)
            s += __shfl_down_sync(0xFFFFFFFFu, s, off);

        __shared__ float fin_sums[8];
        if (lane == 0) fin_sums[wid] = s;
        __syncthreads();

        if (wid == 0) {
            float t = (lane < 8) ? fin_sums[lane] : 0.0f;
            #pragma unroll
            for (int off = 4; off > 0; off >>= 1)
                t += __shfl_down_sync(0xFFFFFFFFu, t, off);
            if (lane == 0) {
                int nb = num_boxes[0] + num_boxes[1] + num_boxes[2] + num_boxes[3];
                out[0] = t / (float)nb;
                g_counter = 0;                 // reset for next graph replay
            }
        }
    }
}

extern "C" void kernel_launch(void* const* d_in, const int* in_sizes, int n_in,
                              void* d_out, int out_size) {
    const float* y_fcn     = (const float*)d_in[0];
    const float* im_data   = (const float*)d_in[1];
    // d_in[2] = im_info (unused)
    const int*   gt_boxes  = (const int*)d_in[3];
    const int*   num_boxes = (const int*)d_in[4];
    float*       out       = (float*)d_out;

    dim3 grid(BATCH * MAXB, NSLICE);
    box_sum_kernel<<<grid, 256>>>(y_fcn, im_data, gt_boxes, num_boxes, out);
}

// round 7
// speedup vs baseline: 1.2600x; 1.2600x over previous
#include <cuda_runtime.h>
#include <cuda_bf16.h>

// Problem constants (fixed by the reference)
#define BATCH 4
#define NCH 3
#define NCLS 20
#define HH 512
#define WW 512
#define MAXB 50
#define NSLICE 16
#define ROWG 8                         // row-groups per block (ty)
#define LANES 32                       // lanes per row-group (x, each handles float4)
#define ROWSTRIDE (NSLICE * ROWG)      // 128-way row interleave per box
#define NJOBS (BATCH * MAXB * NSLICE)  // 3200 jobs; job j -> partial slot j
#define NBLOCKS 592                    // 148 SMs x 4 resident blocks (63 regs)

// Scratch (no allocation): deterministic partial slots + int counters
__device__ float g_partials[NJOBS];
__device__ int   g_ticket  = 0;        // work-stealing ticket
__device__ int   g_counter = 0;        // finished-blocks counter (last-block finalize)

__global__ void __launch_bounds__(256) box_sum_kernel(
    const float* __restrict__ y_fcn,    // [B, NCLS*NCH, H, W]
    const float* __restrict__ im_data,  // [B, NCH, H, W]
    const int*   __restrict__ gt_boxes, // [B, MAXB, 5] (x1,y1,x2,y2,cls)
    const int*   __restrict__ num_boxes,// [B]
    float*       __restrict__ out
) {
    const int tid  = threadIdx.x;
    const int lane = tid & 31;
    const int wid  = tid >> 5;
    const int tx   = tid & (LANES - 1);     // 0..31
    const int ty   = tid / LANES;           // 0..7

    __shared__ int   job_s;
    __shared__ float warp_sums[8];

    const size_t plane = (size_t)HH * WW;

    for (;;) {
        __syncthreads();                     // protect job_s / warp_sums reuse
        if (tid == 0) job_s = atomicAdd(&g_ticket, 1);
        __syncthreads();
        const int j = job_s;
        if (j >= NJOBS) break;

        const int bb    = j / NSLICE;        // 0 .. B*MAXB-1
        const int slice = j % NSLICE;        // 0 .. NSLICE-1
        const int b     = bb / MAXB;
        const int box   = bb % MAXB;

        if (box >= __ldg(&num_boxes[b])) {   // empty job: write slot, next ticket
            if (tid == 0) g_partials[j] = 0.0f;
            continue;
        }

        const int* g  = gt_boxes + bb * 5;
        const int x1  = __ldg(&g[0]);
        const int y1  = __ldg(&g[1]);
        const int x2  = __ldg(&g[2]);
        const int y2  = __ldg(&g[3]);
        const int cls = __ldg(&g[4]);

        // class cls occupies channels [cls*NCH, (cls+1)*NCH) of y_fcn
        const float* yb = y_fcn   + ((size_t)b * (NCLS * NCH) + (size_t)cls * NCH) * plane;
        const float* ib = im_data + (size_t)b * NCH * plane;

        const int vx1 = (x1 + 3) & ~3;       // aligned interior for float4
        const int vx2 = x2 & ~3;
        const int rowWorker = slice * ROWG + ty;   // 0..127

        float acc = 0.0f;

        for (int r = y1 + rowWorker; r < y2; r += ROWSTRIDE) {
            const float* yr0 = yb + (size_t)r * WW;
            const float* yr1 = yr0 + plane;
            const float* yr2 = yr1 + plane;
            const float* ir0 = ib + (size_t)r * WW;
            const float* ir1 = ir0 + plane;
            const float* ir2 = ir1 + plane;

            if (vx1 < vx2) {
                // scalar head: [x1, vx1), width 0..3
                for (int x = x1 + tx; x < vx1; x += LANES) {
                    float d0 = ir0[x] - yr0[x];
                    float d1 = ir1[x] - yr1[x];
                    float d2 = ir2[x] - yr2[x];
                    acc = fmaf(d0, d0, acc);
                    acc = fmaf(d1, d1, acc);
                    acc = fmaf(d2, d2, acc);
                }
                // vector body: [vx1, vx2), 32 lanes x float4 = 128 cols per step
                for (int x = vx1 + tx * 4; x < vx2; x += LANES * 4) {
                    float4 a0 = *(const float4*)(ir0 + x);
                    float4 c0 = *(const float4*)(yr0 + x);
                    float4 a1 = *(const float4*)(ir1 + x);
                    float4 c1 = *(const float4*)(yr1 + x);
                    float4 a2 = *(const float4*)(ir2 + x);
                    float4 c2 = *(const float4*)(yr2 + x);
                    float d;
                    d = a0.x - c0.x; acc = fmaf(d, d, acc);
                    d = a0.y - c0.y; acc = fmaf(d, d, acc);
                    d = a0.z - c0.z; acc = fmaf(d, d, acc);
                    d = a0.w - c0.w; acc = fmaf(d, d, acc);
                    d = a1.x - c1.x; acc = fmaf(d, d, acc);
                    d = a1.y - c1.y; acc = fmaf(d, d, acc);
                    d = a1.z - c1.z; acc = fmaf(d, d, acc);
                    d = a1.w - c1.w; acc = fmaf(d, d, acc);
                    d = a2.x - c2.x; acc = fmaf(d, d, acc);
                    d = a2.y - c2.y; acc = fmaf(d, d, acc);
                    d = a2.z - c2.z; acc = fmaf(d, d, acc);
                    d = a2.w - c2.w; acc = fmaf(d, d, acc);
                }
                // scalar tail: [vx2, x2), width 0..3
                for (int x = vx2 + tx; x < x2; x += LANES) {
                    float d0 = ir0[x] - yr0[x];
                    float d1 = ir1[x] - yr1[x];
                    float d2 = ir2[x] - yr2[x];
                    acc = fmaf(d0, d0, acc);
                    acc = fmaf(d1, d1, acc);
                    acc = fmaf(d2, d2, acc);
                }
            } else {
                // narrow box (< 4 aligned cols): all scalar
                for (int x = x1 + tx; x < x2; x += LANES) {
                    float d0 = ir0[x] - yr0[x];
                    float d1 = ir1[x] - yr1[x];
                    float d2 = ir2[x] - yr2[x];
                    acc = fmaf(d0, d0, acc);
                    acc = fmaf(d1, d1, acc);
                    acc = fmaf(d2, d2, acc);
                }
            }
        }

        const int area = (y2 - y1) * (x2 - x1);
        acc *= 1.0f / (float)(NCH * (area > 1 ? area : 1));  // linear -> same as scaling sum

        // Deterministic block reduction into slot j
        #pragma unroll
        for (int off = 16; off > 0; off >>= 1)
            acc += __shfl_down_sync(0xFFFFFFFFu, acc, off);
        if (lane == 0) warp_sums[wid] = acc;
        __syncthreads();
        if (wid == 0) {
            float s = (lane < 8) ? warp_sums[lane] : 0.0f;
            #pragma unroll
            for (int off = 4; off > 0; off >>= 1)
                s += __shfl_down_sync(0xFFFFFFFFu, s, off);
            if (lane == 0) g_partials[j] = s;
        }
    }

    // ---- last-block-done fused finalize ----
    __shared__ bool is_last;
    if (tid == 0) {
        __threadfence();                       // publish our partials
        int prev = atomicAdd(&g_counter, 1);
        is_last = (prev == NBLOCKS - 1);
    }
    __syncthreads();

    if (is_last) {
        __threadfence();                       // see everyone's partials

        float s = 0.0f;
        #pragma unroll 4
        for (int i = tid; i < NJOBS; i += 256)
            s += g_partials[i];                // fixed order -> deterministic

        #pragma unroll
        for (int off = 16; off > 0; off >>= 1)
            s += __shfl_down_sync(0xFFFFFFFFu, s, off);

        __shared__ float fin_sums[8];
        if (lane == 0) fin_sums[wid] = s;
        __syncthreads();

        if (wid == 0) {
            float t = (lane < 8) ? fin_sums[lane] : 0.0f;
            #pragma unroll
            for (int off = 4; off > 0; off >>= 1)
                t += __shfl_down_sync(0xFFFFFFFFu, t, off);
            if (lane == 0) {
                int nb = num_boxes[0] + num_boxes[1] + num_boxes[2] + num_boxes[3];
                out[0] = t / (float)nb;
                g_ticket  = 0;                 // reset for next graph replay
                g_counter = 0;
            }
        }
    }
}

extern "C" void kernel_launch(void* const* d_in, const int* in_sizes, int n_in,
                              void* d_out, int out_size) {
    const float* y_fcn     = (const float*)d_in[0];
    const float* im_data   = (const float*)d_in[1];
    // d_in[2] = im_info (unused)
    const int*   gt_boxes  = (const int*)d_in[3];
    const int*   num_boxes = (const int*)d_in[4];
    float*       out       = (float*)d_out;

    box_sum_kernel<<<NBLOCKS, 256>>>(y_fcn, im_data, gt_boxes, num_boxes, out);
}